// round 5
// baseline (speedup 1.0000x reference)
#include <cuda_runtime.h>
#include <math.h>

#define B_  64
#define T_  512
#define D_  512
#define H_  1024
#define G4  4096
#define M1  32768          // B_*T_
#define NBLK 128
#define RTH 256

// Recurrence smem: Bs[32][1028] + As2[2][64][68]
#define BS_P 1028
#define AS_W 68
#define R_SMEM_BYTES ((32 * BS_P + 2 * 64 * AS_W) * 4)    // 166400

// Phase-1 smem: As[2][128][36] + Bs[2][64][36]
#define P1_AW 36
#define P1_SMEM_BYTES ((2 * 128 * P1_AW + 2 * 64 * P1_AW) * 4)  // 55296

typedef unsigned long long u64;

// ---------------------------------------------------------------------------
// Device globals (allocation-free scratch)
// ---------------------------------------------------------------------------
__device__ float g_xg[(size_t)M1 * G4];    // xg = x@Wx + b   (512 MB)
__device__ float g_hb[2][B_ * H_];         // double-buffered hidden state
__device__ unsigned g_cnt;                 // grid barrier counter
__device__ unsigned g_gen;                 // grid barrier generation

// ---------------------------------------------------------------------------
// f32x2 helpers
// ---------------------------------------------------------------------------
__device__ __forceinline__ void fma2(u64& d, u64 a, u64 b) {
    asm("fma.rn.f32x2 %0, %1, %2, %0;" : "+l"(d) : "l"(a), "l"(b));
}
__device__ __forceinline__ float red2(u64 v) {
    float lo, hi;
    asm("mov.b64 {%0, %1}, %2;" : "=f"(lo), "=f"(hi) : "l"(v));
    return lo + hi;
}

// ---------------------------------------------------------------------------
// Phase 1: xg[M1, G4] = x[M1, D] @ Wx[D, G4] + bias
// Block tile 128(M) x 64(N), 256 threads, K-pair packed f32x2.
// Lane tile: 4 rows x 8 cols (rows w*16+rl+4i, cols ncol0+8j+cl).
// ---------------------------------------------------------------------------
__global__ void __launch_bounds__(256, 2)
gemm_xw(const float* __restrict__ x,
        const float* __restrict__ Wx,
        const float* __restrict__ bias) {
    extern __shared__ float sm[];
    float* As = sm;                       // [2][128][36]
    float* Bs = sm + 2 * 128 * P1_AW;     // [2][64][36]

    const int bm = blockIdx.y;
    const int bn = blockIdx.x;
    const int tid = threadIdx.x;
    const int w  = tid >> 5;
    const int l  = tid & 31;
    const int rl = l >> 3;     // 0..3
    const int cl = l & 7;      // 0..7
    const int ncol0 = bn * 64;

    // A staging: row = tid>>1 (0..127), kq = (tid&1)*16
    const int s_arow = tid >> 1;
    const int s_akq  = (tid & 1) * 16;
    const float* axp = x + (size_t)(bm * 128 + s_arow) * D_ + s_akq;

    // B staging: kr = tid>>3 (0..31), cgrp = (tid&7)*8
    const int s_bkr = tid >> 3;
    const int s_bc  = (tid & 7) * 8;
    const float* bxp = Wx + (size_t)s_bkr * G4 + ncol0 + s_bc;

    int aoff[4], boff[8];
#pragma unroll
    for (int i = 0; i < 4; ++i) aoff[i] = (w * 16 + rl + 4 * i) * P1_AW;
#pragma unroll
    for (int j = 0; j < 8; ++j) boff[j] = (8 * j + cl) * P1_AW;

    u64 acc[4][8];
#pragma unroll
    for (int i = 0; i < 4; ++i)
#pragma unroll
        for (int j = 0; j < 8; ++j) acc[i][j] = 0ull;

    // prologue: load + stage chunk 0
    float4 av0 = *(const float4*)(axp);
    float4 av1 = *(const float4*)(axp + 4);
    float4 av2 = *(const float4*)(axp + 8);
    float4 av3 = *(const float4*)(axp + 12);
    float4 bw0 = *(const float4*)(bxp);
    float4 bw1 = *(const float4*)(bxp + 4);
    {
        float* Ad = As;
        float* Bd = Bs;
        *(float4*)&Ad[s_arow * P1_AW + s_akq + 0]  = av0;
        *(float4*)&Ad[s_arow * P1_AW + s_akq + 4]  = av1;
        *(float4*)&Ad[s_arow * P1_AW + s_akq + 8]  = av2;
        *(float4*)&Ad[s_arow * P1_AW + s_akq + 12] = av3;
        Bd[(s_bc + 0) * P1_AW + s_bkr] = bw0.x;
        Bd[(s_bc + 1) * P1_AW + s_bkr] = bw0.y;
        Bd[(s_bc + 2) * P1_AW + s_bkr] = bw0.z;
        Bd[(s_bc + 3) * P1_AW + s_bkr] = bw0.w;
        Bd[(s_bc + 4) * P1_AW + s_bkr] = bw1.x;
        Bd[(s_bc + 5) * P1_AW + s_bkr] = bw1.y;
        Bd[(s_bc + 6) * P1_AW + s_bkr] = bw1.z;
        Bd[(s_bc + 7) * P1_AW + s_bkr] = bw1.w;
    }
    __syncthreads();

#pragma unroll 1
    for (int kc = 0; kc < 16; ++kc) {
        if (kc < 15) {
            const float* ap = axp + (kc + 1) * 32;
            const float* bp = bxp + (size_t)(kc + 1) * 32 * G4;
            av0 = *(const float4*)(ap);
            av1 = *(const float4*)(ap + 4);
            av2 = *(const float4*)(ap + 8);
            av3 = *(const float4*)(ap + 12);
            bw0 = *(const float4*)(bp);
            bw1 = *(const float4*)(bp + 4);
        }
        const float* A  = As + (kc & 1) * (128 * P1_AW);
        const float* Bb = Bs + (kc & 1) * (64 * P1_AW);
#pragma unroll
        for (int kk = 0; kk < 32; kk += 4) {
            ulonglong2 a0 = *(const ulonglong2*)(A + aoff[0] + kk);
            ulonglong2 a1 = *(const ulonglong2*)(A + aoff[1] + kk);
            ulonglong2 a2 = *(const ulonglong2*)(A + aoff[2] + kk);
            ulonglong2 a3 = *(const ulonglong2*)(A + aoff[3] + kk);
#pragma unroll
            for (int jh = 0; jh < 2; ++jh) {
                ulonglong2 b0 = *(const ulonglong2*)(Bb + boff[jh * 4 + 0] + kk);
                ulonglong2 b1 = *(const ulonglong2*)(Bb + boff[jh * 4 + 1] + kk);
                ulonglong2 b2 = *(const ulonglong2*)(Bb + boff[jh * 4 + 2] + kk);
                ulonglong2 b3 = *(const ulonglong2*)(Bb + boff[jh * 4 + 3] + kk);
                fma2(acc[0][jh*4+0], a0.x, b0.x); fma2(acc[0][jh*4+1], a0.x, b1.x);
                fma2(acc[0][jh*4+2], a0.x, b2.x); fma2(acc[0][jh*4+3], a0.x, b3.x);
                fma2(acc[1][jh*4+0], a1.x, b0.x); fma2(acc[1][jh*4+1], a1.x, b1.x);
                fma2(acc[1][jh*4+2], a1.x, b2.x); fma2(acc[1][jh*4+3], a1.x, b3.x);
                fma2(acc[2][jh*4+0], a2.x, b0.x); fma2(acc[2][jh*4+1], a2.x, b1.x);
                fma2(acc[2][jh*4+2], a2.x, b2.x); fma2(acc[2][jh*4+3], a2.x, b3.x);
                fma2(acc[3][jh*4+0], a3.x, b0.x); fma2(acc[3][jh*4+1], a3.x, b1.x);
                fma2(acc[3][jh*4+2], a3.x, b2.x); fma2(acc[3][jh*4+3], a3.x, b3.x);
                fma2(acc[0][jh*4+0], a0.y, b0.y); fma2(acc[0][jh*4+1], a0.y, b1.y);
                fma2(acc[0][jh*4+2], a0.y, b2.y); fma2(acc[0][jh*4+3], a0.y, b3.y);
                fma2(acc[1][jh*4+0], a1.y, b0.y); fma2(acc[1][jh*4+1], a1.y, b1.y);
                fma2(acc[1][jh*4+2], a1.y, b2.y); fma2(acc[1][jh*4+3], a1.y, b3.y);
                fma2(acc[2][jh*4+0], a2.y, b0.y); fma2(acc[2][jh*4+1], a2.y, b1.y);
                fma2(acc[2][jh*4+2], a2.y, b2.y); fma2(acc[2][jh*4+3], a2.y, b3.y);
                fma2(acc[3][jh*4+0], a3.y, b0.y); fma2(acc[3][jh*4+1], a3.y, b1.y);
                fma2(acc[3][jh*4+2], a3.y, b2.y); fma2(acc[3][jh*4+3], a3.y, b3.y);
            }
        }
        if (kc < 15) {
            float* Ad = As + ((kc + 1) & 1) * (128 * P1_AW);
            float* Bd = Bs + ((kc + 1) & 1) * (64 * P1_AW);
            *(float4*)&Ad[s_arow * P1_AW + s_akq + 0]  = av0;
            *(float4*)&Ad[s_arow * P1_AW + s_akq + 4]  = av1;
            *(float4*)&Ad[s_arow * P1_AW + s_akq + 8]  = av2;
            *(float4*)&Ad[s_arow * P1_AW + s_akq + 12] = av3;
            Bd[(s_bc + 0) * P1_AW + s_bkr] = bw0.x;
            Bd[(s_bc + 1) * P1_AW + s_bkr] = bw0.y;
            Bd[(s_bc + 2) * P1_AW + s_bkr] = bw0.z;
            Bd[(s_bc + 3) * P1_AW + s_bkr] = bw0.w;
            Bd[(s_bc + 4) * P1_AW + s_bkr] = bw1.x;
            Bd[(s_bc + 5) * P1_AW + s_bkr] = bw1.y;
            Bd[(s_bc + 6) * P1_AW + s_bkr] = bw1.z;
            Bd[(s_bc + 7) * P1_AW + s_bkr] = bw1.w;
        }
        __syncthreads();
    }

    // Epilogue: reduce k-pairs, add bias, store
    float bb[8];
#pragma unroll
    for (int j = 0; j < 8; ++j) bb[j] = bias[ncol0 + 8 * j + cl];
#pragma unroll
    for (int i = 0; i < 4; ++i) {
        size_t row = (size_t)(bm * 128 + w * 16 + rl + 4 * i);
        float* crow = g_xg + row * G4 + ncol0 + cl;
#pragma unroll
        for (int j = 0; j < 8; ++j)
            crow[8 * j] = red2(acc[i][j]) + bb[j];
    }
}

// ---------------------------------------------------------------------------
// Init: zero h buffer 0 and barrier counter
// ---------------------------------------------------------------------------
__global__ void init_state() {
    int idx = blockIdx.x * blockDim.x + threadIdx.x;
    g_hb[0][idx] = 0.0f;
    if (idx == 0) g_cnt = 0u;
}

// ---------------------------------------------------------------------------
// Grid-wide barrier (all NBLK blocks resident)
// ---------------------------------------------------------------------------
__device__ __forceinline__ void grid_barrier() {
    __threadfence();
    __syncthreads();
    if (threadIdx.x == 0) {
        volatile unsigned* vg = &g_gen;
        unsigned gen = *vg;
        if (atomicAdd(&g_cnt, 1u) == NBLK - 1) {
            atomicExch(&g_cnt, 0u);
            __threadfence();
            atomicAdd((unsigned*)&g_gen, 1u);
        } else {
            while (*vg == gen) { }
        }
    }
    __syncthreads();
}

// ---------------------------------------------------------------------------
// Persistent recurrence. Block owns 8 hidden cols (32 gate-cols).
// Bs[g*8+jj][k] (K-major per col, padded 1028) resident all 512 steps.
// Lane tile: rows {w*8+rl, w*8+rl+4} x all 4 gates of hidden col j0+cl.
// K-pair packed: acc u64 += (h_k,h_k+1)*(W_k,W_k+1); reduce at step end.
// Per 4k: 6 LDS.128 + 16 fma2 (FMA-bound @16 cyc/k/SMSP).
// ---------------------------------------------------------------------------
__global__ void __launch_bounds__(RTH, 1)
lstm_persist(const float* __restrict__ Wh, float* __restrict__ out) {
    extern __shared__ float sm[];
    float* Bs  = sm;                      // [32][1028]
    float* As2 = sm + 32 * BS_P;          // [2][64][68]

    const int tid = threadIdx.x;
    const int w  = tid >> 5;
    const int l  = tid & 31;
    const int rl = l >> 3;      // 0..3
    const int cl = l & 7;       // 0..7
    const int j0 = blockIdx.x * 8;

    // One-time Wh slice load: Bs[(g*8+jj)][k] = Wh[k][g*H + j0 + jj]
    for (int idx = tid; idx < 32 * 1024; idx += RTH) {
        int c = idx >> 10, k = idx & 1023;
        Bs[c * BS_P + k] = Wh[(size_t)k * G4 + (c >> 3) * H_ + j0 + (c & 7)];
    }

    const int aoff0 = (w * 8 + rl) * AS_W;
    const int aoff1 = aoff0 + 4 * AS_W;
    const float* bp0 = Bs + (0 * 8 + cl) * BS_P;
    const float* bp1 = Bs + (1 * 8 + cl) * BS_P;
    const float* bp2 = Bs + (2 * 8 + cl) * BS_P;
    const float* bp3 = Bs + (3 * 8 + cl) * BS_P;

    // staging: srow = tid&63, sq = tid>>6 (16 floats per thread per 64k chunk)
    const int srow = tid & 63;
    const int sq   = tid >> 6;
    const int soff = srow * AS_W + sq * 16;

    const int r0 = w * 8 + rl;
    const int r1 = r0 + 4;
    const int j  = j0 + cl;

    float cc0 = 0.f, cc1 = 0.f;
    __syncthreads();

    for (int t = 0; t < T_; ++t) {
        const float* hin  = g_hb[t & 1];
        float*       hout = g_hb[(t + 1) & 1];

        // prefetch xg gates for the epilogue (streaming)
        const float* xb0 = g_xg + ((size_t)r0 * T_ + t) * G4 + j;
        const float* xb1 = g_xg + ((size_t)r1 * T_ + t) * G4 + j;
        float xi0 = __ldcs(xb0);           float xi1 = __ldcs(xb1);
        float xf0 = __ldcs(xb0 + H_);      float xf1 = __ldcs(xb1 + H_);
        float xg0 = __ldcs(xb0 + 2 * H_);  float xg1 = __ldcs(xb1 + 2 * H_);
        float xo0 = __ldcs(xb0 + 3 * H_);  float xo1 = __ldcs(xb1 + 3 * H_);

        u64 a00 = 0, a01 = 0, a02 = 0, a03 = 0;   // row r0, gates i f g o
        u64 a10 = 0, a11 = 0, a12 = 0, a13 = 0;   // row r1

        // stage chunk 0
        {
            const float* hp = hin + srow * H_ + sq * 16;
            float4 p0 = __ldcg((const float4*)(hp));
            float4 p1 = __ldcg((const float4*)(hp + 4));
            float4 p2 = __ldcg((const float4*)(hp + 8));
            float4 p3 = __ldcg((const float4*)(hp + 12));
            *(float4*)&As2[soff + 0]  = p0;
            *(float4*)&As2[soff + 4]  = p1;
            *(float4*)&As2[soff + 8]  = p2;
            *(float4*)&As2[soff + 12] = p3;
        }
        __syncthreads();

#pragma unroll 1
        for (int kc = 0; kc < 16; ++kc) {
            float4 q0, q1, q2, q3;
            if (kc < 15) {
                const float* hp = hin + srow * H_ + (kc + 1) * 64 + sq * 16;
                q0 = __ldcg((const float4*)(hp));
                q1 = __ldcg((const float4*)(hp + 4));
                q2 = __ldcg((const float4*)(hp + 8));
                q3 = __ldcg((const float4*)(hp + 12));
            }
            const float* A = As2 + (kc & 1) * (64 * AS_W);
            const int kg = kc * 64;
#pragma unroll
            for (int kk = 0; kk < 64; kk += 4) {
                ulonglong2 av0 = *(const ulonglong2*)(A + aoff0 + kk);
                ulonglong2 av1 = *(const ulonglong2*)(A + aoff1 + kk);
                ulonglong2 b0  = *(const ulonglong2*)(bp0 + kg + kk);
                ulonglong2 b1  = *(const ulonglong2*)(bp1 + kg + kk);
                ulonglong2 b2  = *(const ulonglong2*)(bp2 + kg + kk);
                ulonglong2 b3  = *(const ulonglong2*)(bp3 + kg + kk);
                fma2(a00, av0.x, b0.x); fma2(a01, av0.x, b1.x);
                fma2(a02, av0.x, b2.x); fma2(a03, av0.x, b3.x);
                fma2(a10, av1.x, b0.x); fma2(a11, av1.x, b1.x);
                fma2(a12, av1.x, b2.x); fma2(a13, av1.x, b3.x);
                fma2(a00, av0.y, b0.y); fma2(a01, av0.y, b1.y);
                fma2(a02, av0.y, b2.y); fma2(a03, av0.y, b3.y);
                fma2(a10, av1.y, b0.y); fma2(a11, av1.y, b1.y);
                fma2(a12, av1.y, b2.y); fma2(a13, av1.y, b3.y);
            }
            if (kc < 15) {
                float* Ad = As2 + ((kc + 1) & 1) * (64 * AS_W);
                *(float4*)&Ad[soff + 0]  = q0;
                *(float4*)&Ad[soff + 4]  = q1;
                *(float4*)&Ad[soff + 8]  = q2;
                *(float4*)&Ad[soff + 12] = q3;
            }
            __syncthreads();
        }

        // Pointwise cells (2 per lane, fully local)
        {
            float vi = red2(a00) + xi0;
            float vf = red2(a01) + xf0;
            float vg = red2(a02) + xg0;
            float vo = red2(a03) + xo0;
            float si = 1.0f / (1.0f + expf(-vi));
            float sf = 1.0f / (1.0f + expf(-vf));
            float tg = tanhf(vg);
            float so = 1.0f / (1.0f + expf(-vo));
            float c = sf * cc0 + si * tg;
            cc0 = c;
            float h = so * tanhf(c);
            hout[r0 * H_ + j] = h;
            out[((size_t)r0 * T_ + t) * H_ + j] = h;
        }
        {
            float vi = red2(a10) + xi1;
            float vf = red2(a11) + xf1;
            float vg = red2(a12) + xg1;
            float vo = red2(a13) + xo1;
            float si = 1.0f / (1.0f + expf(-vi));
            float sf = 1.0f / (1.0f + expf(-vf));
            float tg = tanhf(vg);
            float so = 1.0f / (1.0f + expf(-vo));
            float c = sf * cc1 + si * tg;
            cc1 = c;
            float h = so * tanhf(c);
            hout[r1 * H_ + j] = h;
            out[((size_t)r1 * T_ + t) * H_ + j] = h;
        }

        if (t < T_ - 1) grid_barrier();
    }
}

// ---------------------------------------------------------------------------
// Launch: 3 graph nodes
// ---------------------------------------------------------------------------
extern "C" void kernel_launch(void* const* d_in, const int* in_sizes, int n_in,
                              void* d_out, int out_size) {
    const float* x    = (const float*)d_in[0];   // [B, T, D]
    const float* Wx   = (const float*)d_in[1];   // [D, 4H]
    const float* Wh   = (const float*)d_in[2];   // [H, 4H]
    const float* bias = (const float*)d_in[3];   // [4H]
    float* out = (float*)d_out;                  // [B, T, H]

    cudaFuncSetAttribute(lstm_persist,
                         cudaFuncAttributeMaxDynamicSharedMemorySize, R_SMEM_BYTES);
    cudaFuncSetAttribute(gemm_xw,
                         cudaFuncAttributeMaxDynamicSharedMemorySize, P1_SMEM_BYTES);

    dim3 g1(G4 / 64, M1 / 128);                  // (64, 256)
    gemm_xw<<<g1, 256, P1_SMEM_BYTES>>>(x, Wx, bias);
    init_state<<<256, 256>>>();
    lstm_persist<<<NBLK, RTH, R_SMEM_BYTES>>>(Wh, out);
}

// round 6
// speedup vs baseline: 1.0018x; 1.0018x over previous
#include <cuda_runtime.h>
#include <math.h>

#define B_  64
#define T_  512
#define D_  512
#define H_  1024
#define G4  4096
#define M1  32768          // B_*T_
#define NBLK 128
#define RTH 256

// Recurrence smem: Bs[32][1028] + As2[2][64][68]
#define BS_P 1028
#define AS_W 68
#define R_SMEM_BYTES ((32 * BS_P + 2 * 64 * AS_W) * 4)    // 166400

// Phase-1 smem: As[2][128][36] + Bs[2][64][36]
#define P1_AW 36
#define P1_SMEM_BYTES ((2 * 128 * P1_AW + 2 * 64 * P1_AW) * 4)  // 55296

typedef unsigned long long u64;

// ---------------------------------------------------------------------------
// Device globals (allocation-free scratch)
// ---------------------------------------------------------------------------
__device__ float g_xg[(size_t)M1 * G4];    // xg = x@Wx + b   (512 MB)
__device__ float g_hb[2][B_ * H_];         // double-buffered hidden state
__device__ unsigned g_cnt;                 // grid barrier counter
__device__ unsigned g_gen;                 // grid barrier generation

// ---------------------------------------------------------------------------
// f32x2 helpers
// ---------------------------------------------------------------------------
__device__ __forceinline__ void fma2(u64& d, u64 a, u64 b) {
    asm("fma.rn.f32x2 %0, %1, %2, %0;" : "+l"(d) : "l"(a), "l"(b));
}
__device__ __forceinline__ float red2(u64 v) {
    float lo, hi;
    asm("mov.b64 {%0, %1}, %2;" : "=f"(lo), "=f"(hi) : "l"(v));
    return lo + hi;
}

// ---------------------------------------------------------------------------
// Phase 1: xg[M1, G4] = x[M1, D] @ Wx[D, G4] + bias
// Block tile 128(M) x 64(N), 256 threads, K-pair packed f32x2.
// Lane tile: 4 rows x 8 cols (rows w*16+rl+4i, cols ncol0+8j+cl).
// ---------------------------------------------------------------------------
__global__ void __launch_bounds__(256, 2)
gemm_xw(const float* __restrict__ x,
        const float* __restrict__ Wx,
        const float* __restrict__ bias) {
    extern __shared__ float sm[];
    float* As = sm;                       // [2][128][36]
    float* Bs = sm + 2 * 128 * P1_AW;     // [2][64][36]

    const int bm = blockIdx.y;
    const int bn = blockIdx.x;
    const int tid = threadIdx.x;
    const int w  = tid >> 5;
    const int l  = tid & 31;
    const int rl = l >> 3;     // 0..3
    const int cl = l & 7;      // 0..7
    const int ncol0 = bn * 64;

    // A staging: row = tid>>1 (0..127), kq = (tid&1)*16
    const int s_arow = tid >> 1;
    const int s_akq  = (tid & 1) * 16;
    const float* axp = x + (size_t)(bm * 128 + s_arow) * D_ + s_akq;

    // B staging: kr = tid>>3 (0..31), cgrp = (tid&7)*8
    const int s_bkr = tid >> 3;
    const int s_bc  = (tid & 7) * 8;
    const float* bxp = Wx + (size_t)s_bkr * G4 + ncol0 + s_bc;

    int aoff[4], boff[8];
#pragma unroll
    for (int i = 0; i < 4; ++i) aoff[i] = (w * 16 + rl + 4 * i) * P1_AW;
#pragma unroll
    for (int j = 0; j < 8; ++j) boff[j] = (8 * j + cl) * P1_AW;

    u64 acc[4][8];
#pragma unroll
    for (int i = 0; i < 4; ++i)
#pragma unroll
        for (int j = 0; j < 8; ++j) acc[i][j] = 0ull;

    // prologue: load + stage chunk 0
    float4 av0 = *(const float4*)(axp);
    float4 av1 = *(const float4*)(axp + 4);
    float4 av2 = *(const float4*)(axp + 8);
    float4 av3 = *(const float4*)(axp + 12);
    float4 bw0 = *(const float4*)(bxp);
    float4 bw1 = *(const float4*)(bxp + 4);
    {
        float* Ad = As;
        float* Bd = Bs;
        *(float4*)&Ad[s_arow * P1_AW + s_akq + 0]  = av0;
        *(float4*)&Ad[s_arow * P1_AW + s_akq + 4]  = av1;
        *(float4*)&Ad[s_arow * P1_AW + s_akq + 8]  = av2;
        *(float4*)&Ad[s_arow * P1_AW + s_akq + 12] = av3;
        Bd[(s_bc + 0) * P1_AW + s_bkr] = bw0.x;
        Bd[(s_bc + 1) * P1_AW + s_bkr] = bw0.y;
        Bd[(s_bc + 2) * P1_AW + s_bkr] = bw0.z;
        Bd[(s_bc + 3) * P1_AW + s_bkr] = bw0.w;
        Bd[(s_bc + 4) * P1_AW + s_bkr] = bw1.x;
        Bd[(s_bc + 5) * P1_AW + s_bkr] = bw1.y;
        Bd[(s_bc + 6) * P1_AW + s_bkr] = bw1.z;
        Bd[(s_bc + 7) * P1_AW + s_bkr] = bw1.w;
    }
    __syncthreads();

#pragma unroll 1
    for (int kc = 0; kc < 16; ++kc) {
        if (kc < 15) {
            const float* ap = axp + (kc + 1) * 32;
            const float* bp = bxp + (size_t)(kc + 1) * 32 * G4;
            av0 = *(const float4*)(ap);
            av1 = *(const float4*)(ap + 4);
            av2 = *(const float4*)(ap + 8);
            av3 = *(const float4*)(ap + 12);
            bw0 = *(const float4*)(bp);
            bw1 = *(const float4*)(bp + 4);
        }
        const float* A  = As + (kc & 1) * (128 * P1_AW);
        const float* Bb = Bs + (kc & 1) * (64 * P1_AW);
#pragma unroll
        for (int kk = 0; kk < 32; kk += 4) {
            ulonglong2 a0 = *(const ulonglong2*)(A + aoff[0] + kk);
            ulonglong2 a1 = *(const ulonglong2*)(A + aoff[1] + kk);
            ulonglong2 a2 = *(const ulonglong2*)(A + aoff[2] + kk);
            ulonglong2 a3 = *(const ulonglong2*)(A + aoff[3] + kk);
#pragma unroll
            for (int jh = 0; jh < 2; ++jh) {
                ulonglong2 b0 = *(const ulonglong2*)(Bb + boff[jh * 4 + 0] + kk);
                ulonglong2 b1 = *(const ulonglong2*)(Bb + boff[jh * 4 + 1] + kk);
                ulonglong2 b2 = *(const ulonglong2*)(Bb + boff[jh * 4 + 2] + kk);
                ulonglong2 b3 = *(const ulonglong2*)(Bb + boff[jh * 4 + 3] + kk);
                fma2(acc[0][jh*4+0], a0.x, b0.x); fma2(acc[0][jh*4+1], a0.x, b1.x);
                fma2(acc[0][jh*4+2], a0.x, b2.x); fma2(acc[0][jh*4+3], a0.x, b3.x);
                fma2(acc[1][jh*4+0], a1.x, b0.x); fma2(acc[1][jh*4+1], a1.x, b1.x);
                fma2(acc[1][jh*4+2], a1.x, b2.x); fma2(acc[1][jh*4+3], a1.x, b3.x);
                fma2(acc[2][jh*4+0], a2.x, b0.x); fma2(acc[2][jh*4+1], a2.x, b1.x);
                fma2(acc[2][jh*4+2], a2.x, b2.x); fma2(acc[2][jh*4+3], a2.x, b3.x);
                fma2(acc[3][jh*4+0], a3.x, b0.x); fma2(acc[3][jh*4+1], a3.x, b1.x);
                fma2(acc[3][jh*4+2], a3.x, b2.x); fma2(acc[3][jh*4+3], a3.x, b3.x);
                fma2(acc[0][jh*4+0], a0.y, b0.y); fma2(acc[0][jh*4+1], a0.y, b1.y);
                fma2(acc[0][jh*4+2], a0.y, b2.y); fma2(acc[0][jh*4+3], a0.y, b3.y);
                fma2(acc[1][jh*4+0], a1.y, b0.y); fma2(acc[1][jh*4+1], a1.y, b1.y);
                fma2(acc[1][jh*4+2], a1.y, b2.y); fma2(acc[1][jh*4+3], a1.y, b3.y);
                fma2(acc[2][jh*4+0], a2.y, b0.y); fma2(acc[2][jh*4+1], a2.y, b1.y);
                fma2(acc[2][jh*4+2], a2.y, b2.y); fma2(acc[2][jh*4+3], a2.y, b3.y);
                fma2(acc[3][jh*4+0], a3.y, b0.y); fma2(acc[3][jh*4+1], a3.y, b1.y);
                fma2(acc[3][jh*4+2], a3.y, b2.y); fma2(acc[3][jh*4+3], a3.y, b3.y);
            }
        }
        if (kc < 15) {
            float* Ad = As + ((kc + 1) & 1) * (128 * P1_AW);
            float* Bd = Bs + ((kc + 1) & 1) * (64 * P1_AW);
            *(float4*)&Ad[s_arow * P1_AW + s_akq + 0]  = av0;
            *(float4*)&Ad[s_arow * P1_AW + s_akq + 4]  = av1;
            *(float4*)&Ad[s_arow * P1_AW + s_akq + 8]  = av2;
            *(float4*)&Ad[s_arow * P1_AW + s_akq + 12] = av3;
            Bd[(s_bc + 0) * P1_AW + s_bkr] = bw0.x;
            Bd[(s_bc + 1) * P1_AW + s_bkr] = bw0.y;
            Bd[(s_bc + 2) * P1_AW + s_bkr] = bw0.z;
            Bd[(s_bc + 3) * P1_AW + s_bkr] = bw0.w;
            Bd[(s_bc + 4) * P1_AW + s_bkr] = bw1.x;
            Bd[(s_bc + 5) * P1_AW + s_bkr] = bw1.y;
            Bd[(s_bc + 6) * P1_AW + s_bkr] = bw1.z;
            Bd[(s_bc + 7) * P1_AW + s_bkr] = bw1.w;
        }
        __syncthreads();
    }

    // Epilogue: reduce k-pairs, add bias, store
    float bb[8];
#pragma unroll
    for (int j = 0; j < 8; ++j) bb[j] = bias[ncol0 + 8 * j + cl];
#pragma unroll
    for (int i = 0; i < 4; ++i) {
        size_t row = (size_t)(bm * 128 + w * 16 + rl + 4 * i);
        float* crow = g_xg + row * G4 + ncol0 + cl;
#pragma unroll
        for (int j = 0; j < 8; ++j)
            crow[8 * j] = red2(acc[i][j]) + bb[j];
    }
}

// ---------------------------------------------------------------------------
// Init: zero h buffer 0 and barrier counter
// ---------------------------------------------------------------------------
__global__ void init_state() {
    int idx = blockIdx.x * blockDim.x + threadIdx.x;
    g_hb[0][idx] = 0.0f;
    if (idx == 0) g_cnt = 0u;
}

// ---------------------------------------------------------------------------
// Grid-wide barrier (all NBLK blocks resident)
// ---------------------------------------------------------------------------
__device__ __forceinline__ void grid_barrier() {
    __threadfence();
    __syncthreads();
    if (threadIdx.x == 0) {
        volatile unsigned* vg = &g_gen;
        unsigned gen = *vg;
        if (atomicAdd(&g_cnt, 1u) == NBLK - 1) {
            atomicExch(&g_cnt, 0u);
            __threadfence();
            atomicAdd((unsigned*)&g_gen, 1u);
        } else {
            while (*vg == gen) { }
        }
    }
    __syncthreads();
}

// ---------------------------------------------------------------------------
// Persistent recurrence. Block owns 8 hidden cols (32 gate-cols).
// Bs[g*8+jj][k] (K-major per col, padded 1028) resident all 512 steps.
// Lane tile: rows {w*8+rl, w*8+rl+4} x all 4 gates of hidden col j0+cl.
// K-pair packed: acc u64 += (h_k,h_k+1)*(W_k,W_k+1); reduce at step end.
// Per 4k: 6 LDS.128 + 16 fma2 (FMA-bound @16 cyc/k/SMSP).
// ---------------------------------------------------------------------------
__global__ void __launch_bounds__(RTH, 1)
lstm_persist(const float* __restrict__ Wh, float* __restrict__ out) {
    extern __shared__ float sm[];
    float* Bs  = sm;                      // [32][1028]
    float* As2 = sm + 32 * BS_P;          // [2][64][68]

    const int tid = threadIdx.x;
    const int w  = tid >> 5;
    const int l  = tid & 31;
    const int rl = l >> 3;      // 0..3
    const int cl = l & 7;       // 0..7
    const int j0 = blockIdx.x * 8;

    // One-time Wh slice load: Bs[(g*8+jj)][k] = Wh[k][g*H + j0 + jj]
    for (int idx = tid; idx < 32 * 1024; idx += RTH) {
        int c = idx >> 10, k = idx & 1023;
        Bs[c * BS_P + k] = Wh[(size_t)k * G4 + (c >> 3) * H_ + j0 + (c & 7)];
    }

    const int aoff0 = (w * 8 + rl) * AS_W;
    const int aoff1 = aoff0 + 4 * AS_W;
    const float* bp0 = Bs + (0 * 8 + cl) * BS_P;
    const float* bp1 = Bs + (1 * 8 + cl) * BS_P;
    const float* bp2 = Bs + (2 * 8 + cl) * BS_P;
    const float* bp3 = Bs + (3 * 8 + cl) * BS_P;

    // staging: srow = tid&63, sq = tid>>6 (16 floats per thread per 64k chunk)
    const int srow = tid & 63;
    const int sq   = tid >> 6;
    const int soff = srow * AS_W + sq * 16;

    const int r0 = w * 8 + rl;
    const int r1 = r0 + 4;
    const int j  = j0 + cl;

    float cc0 = 0.f, cc1 = 0.f;
    __syncthreads();

    for (int t = 0; t < T_; ++t) {
        const float* hin  = g_hb[t & 1];
        float*       hout = g_hb[(t + 1) & 1];

        // prefetch xg gates for the epilogue (streaming)
        const float* xb0 = g_xg + ((size_t)r0 * T_ + t) * G4 + j;
        const float* xb1 = g_xg + ((size_t)r1 * T_ + t) * G4 + j;
        float xi0 = __ldcs(xb0);           float xi1 = __ldcs(xb1);
        float xf0 = __ldcs(xb0 + H_);      float xf1 = __ldcs(xb1 + H_);
        float xg0 = __ldcs(xb0 + 2 * H_);  float xg1 = __ldcs(xb1 + 2 * H_);
        float xo0 = __ldcs(xb0 + 3 * H_);  float xo1 = __ldcs(xb1 + 3 * H_);

        u64 a00 = 0, a01 = 0, a02 = 0, a03 = 0;   // row r0, gates i f g o
        u64 a10 = 0, a11 = 0, a12 = 0, a13 = 0;   // row r1

        // stage chunk 0
        {
            const float* hp = hin + srow * H_ + sq * 16;
            float4 p0 = __ldcg((const float4*)(hp));
            float4 p1 = __ldcg((const float4*)(hp + 4));
            float4 p2 = __ldcg((const float4*)(hp + 8));
            float4 p3 = __ldcg((const float4*)(hp + 12));
            *(float4*)&As2[soff + 0]  = p0;
            *(float4*)&As2[soff + 4]  = p1;
            *(float4*)&As2[soff + 8]  = p2;
            *(float4*)&As2[soff + 12] = p3;
        }
        __syncthreads();

#pragma unroll 1
        for (int kc = 0; kc < 16; ++kc) {
            float4 q0, q1, q2, q3;
            if (kc < 15) {
                const float* hp = hin + srow * H_ + (kc + 1) * 64 + sq * 16;
                q0 = __ldcg((const float4*)(hp));
                q1 = __ldcg((const float4*)(hp + 4));
                q2 = __ldcg((const float4*)(hp + 8));
                q3 = __ldcg((const float4*)(hp + 12));
            }
            const float* A = As2 + (kc & 1) * (64 * AS_W);
            const int kg = kc * 64;
#pragma unroll
            for (int kk = 0; kk < 64; kk += 4) {
                ulonglong2 av0 = *(const ulonglong2*)(A + aoff0 + kk);
                ulonglong2 av1 = *(const ulonglong2*)(A + aoff1 + kk);
                ulonglong2 b0  = *(const ulonglong2*)(bp0 + kg + kk);
                ulonglong2 b1  = *(const ulonglong2*)(bp1 + kg + kk);
                ulonglong2 b2  = *(const ulonglong2*)(bp2 + kg + kk);
                ulonglong2 b3  = *(const ulonglong2*)(bp3 + kg + kk);
                fma2(a00, av0.x, b0.x); fma2(a01, av0.x, b1.x);
                fma2(a02, av0.x, b2.x); fma2(a03, av0.x, b3.x);
                fma2(a10, av1.x, b0.x); fma2(a11, av1.x, b1.x);
                fma2(a12, av1.x, b2.x); fma2(a13, av1.x, b3.x);
                fma2(a00, av0.y, b0.y); fma2(a01, av0.y, b1.y);
                fma2(a02, av0.y, b2.y); fma2(a03, av0.y, b3.y);
                fma2(a10, av1.y, b0.y); fma2(a11, av1.y, b1.y);
                fma2(a12, av1.y, b2.y); fma2(a13, av1.y, b3.y);
            }
            if (kc < 15) {
                float* Ad = As2 + ((kc + 1) & 1) * (64 * AS_W);
                *(float4*)&Ad[soff + 0]  = q0;
                *(float4*)&Ad[soff + 4]  = q1;
                *(float4*)&Ad[soff + 8]  = q2;
                *(float4*)&Ad[soff + 12] = q3;
            }
            __syncthreads();
        }

        // Pointwise cells (2 per lane, fully local)
        {
            float vi = red2(a00) + xi0;
            float vf = red2(a01) + xf0;
            float vg = red2(a02) + xg0;
            float vo = red2(a03) + xo0;
            float si = 1.0f / (1.0f + expf(-vi));
            float sf = 1.0f / (1.0f + expf(-vf));
            float tg = tanhf(vg);
            float so = 1.0f / (1.0f + expf(-vo));
            float c = sf * cc0 + si * tg;
            cc0 = c;
            float h = so * tanhf(c);
            hout[r0 * H_ + j] = h;
            out[((size_t)r0 * T_ + t) * H_ + j] = h;
        }
        {
            float vi = red2(a10) + xi1;
            float vf = red2(a11) + xf1;
            float vg = red2(a12) + xg1;
            float vo = red2(a13) + xo1;
            float si = 1.0f / (1.0f + expf(-vi));
            float sf = 1.0f / (1.0f + expf(-vf));
            float tg = tanhf(vg);
            float so = 1.0f / (1.0f + expf(-vo));
            float c = sf * cc1 + si * tg;
            cc1 = c;
            float h = so * tanhf(c);
            hout[r1 * H_ + j] = h;
            out[((size_t)r1 * T_ + t) * H_ + j] = h;
        }

        if (t < T_ - 1) grid_barrier();
    }
}

// ---------------------------------------------------------------------------
// Launch: 3 graph nodes
// ---------------------------------------------------------------------------
extern "C" void kernel_launch(void* const* d_in, const int* in_sizes, int n_in,
                              void* d_out, int out_size) {
    const float* x    = (const float*)d_in[0];   // [B, T, D]
    const float* Wx   = (const float*)d_in[1];   // [D, 4H]
    const float* Wh   = (const float*)d_in[2];   // [H, 4H]
    const float* bias = (const float*)d_in[3];   // [4H]
    float* out = (float*)d_out;                  // [B, T, H]

    cudaFuncSetAttribute(lstm_persist,
                         cudaFuncAttributeMaxDynamicSharedMemorySize, R_SMEM_BYTES);
    cudaFuncSetAttribute(gemm_xw,
                         cudaFuncAttributeMaxDynamicSharedMemorySize, P1_SMEM_BYTES);

    dim3 g1(G4 / 64, M1 / 128);                  // (64, 256)
    gemm_xw<<<g1, 256, P1_SMEM_BYTES>>>(x, Wx, bias);
    init_state<<<256, 256>>>();
    lstm_persist<<<NBLK, RTH, R_SMEM_BYTES>>>(Wh, out);
}